// round 16
// baseline (speedup 1.0000x reference)
#include <cuda_runtime.h>

#define NN 250000
#define EE 2500000
#define GG 2048
#define KK 30
#define HD 32

// -------- scratch (static device globals; no runtime allocation) --------
// g_zero: [0,NN)=degcnt, [NN,NN+64)=bins, [NN+64,NN+128)=bincur, [NN+128]=total
__device__ int   g_zero[NN + 129];
#define DEG(i)  g_zero[i]
#define BINS(b) g_zero[NN + (b)]
#define BCUR(b) g_zero[NN + 64 + (b)]
#define TOT     g_zero[NN + 128]
__device__ float g_dis[NN];
__device__ int   g_nstart[NN];
__device__ int   g_cursor[NN];
__device__ int   g_perm[NN];
__device__ int   g_csr[EE];          // src index only (dis folded into features)
__device__ float g_bufA[(size_t)NN * HD];
__device__ float g_bufB[(size_t)NN * HD];
__device__ float g_pool[(size_t)GG * KK * HD];

// -------- prologue --------
__global__ void k_count(const int* __restrict__ dst) {
    int e = blockIdx.x * blockDim.x + threadIdx.x;
    if (e < EE) atomicAdd(&g_zero[dst[e]], 1);   // DEG region
}

// dis + bump allocation (warp-aggregated) + degree histogram + layer-1 dense
__global__ void __launch_bounds__(256) k_disalloc_mm(const float* __restrict__ X,
                                                     const float* __restrict__ W,
                                                     float* __restrict__ Hp) {
    __shared__ float sW[9 * HD];
    __shared__ int sBin[64];
    for (int i = threadIdx.x; i < 9 * HD; i += blockDim.x) sW[i] = W[i];
    if (threadIdx.x < 64) sBin[threadIdx.x] = 0;

    int i = blockIdx.x * blockDim.x + threadIdx.x;
    int lane = threadIdx.x & 31;
    int deg = (i < NN) ? DEG(i) : 0;
    float d = rsqrtf((float)deg + 1.0f);
    if (i < NN) g_dis[i] = d;
    int scan = deg;
#pragma unroll
    for (int o = 1; o < 32; o <<= 1) {
        int t = __shfl_up_sync(0xffffffffu, scan, o);
        if (lane >= o) scan += t;
    }
    int wsum = __shfl_sync(0xffffffffu, scan, 31);
    int base = 0;
    if (lane == 31) base = atomicAdd(&TOT, wsum);
    base = __shfl_sync(0xffffffffu, base, 31);
    int st = base + scan - deg;
    if (i < NN) {
        g_nstart[i] = st;
        g_cursor[i] = st;
    }
    __syncthreads();
    if (i < NN) atomicAdd(&sBin[deg < 63 ? deg : 63], 1);
    __syncthreads();
    if (threadIdx.x < 64 && sBin[threadIdx.x]) atomicAdd(&BINS(threadIdx.x), sBin[threadIdx.x]);
    if (i >= NN) return;

    float xin[9];
#pragma unroll
    for (int k = 0; k < 9; k++) xin[k] = X[(size_t)i * 9 + k];
    float out[HD];
#pragma unroll
    for (int f = 0; f < HD; f++) {
        float acc = 0.f;
#pragma unroll
        for (int k = 0; k < 9; k++) acc = fmaf(xin[k], sW[k * HD + f], acc);
        out[f] = acc * d;
    }
    float4* ph = (float4*)(Hp + (size_t)i * HD);
#pragma unroll
    for (int q = 0; q < HD / 4; q++) ph[q] = ((float4*)out)[q];
}

// CSR scatter (edge-parallel) + degree-bin permutation (node-parallel) fused.
__global__ void __launch_bounds__(256) k_scatter_permute(const int* __restrict__ src,
                                                         const int* __restrict__ dst) {
    __shared__ int sCnt[64];
    __shared__ int sCur[64];
    __shared__ int sBase[64];
    __shared__ int sExc[64];
    __shared__ int sWs;
    int tid = threadIdx.x;
    if (tid < 64) { sCnt[tid] = 0; sCur[tid] = 0; }

    // edge part
    int e = blockIdx.x * blockDim.x + tid;
    if (e < EE) {
        int d = dst[e];
        int p = atomicAdd(&g_cursor[d], 1);
        g_csr[p] = src[e];
    }

    // node part
    int i = e;
    bool valid = i < NN;
    __syncthreads();
    int b = 0;
    if (valid) {
        int deg = DEG(i);
        b = deg < 63 ? deg : 63;
        atomicAdd(&sCnt[b], 1);
    }
    __syncthreads();
    if (tid < 64) {
        int c = sCnt[tid];
        sBase[tid] = c ? atomicAdd(&BCUR(tid), c) : 0;
        int v = BINS(tid);
        int lane = tid & 31;
        int scan = v;
#pragma unroll
        for (int o = 1; o < 32; o <<= 1) {
            int t = __shfl_up_sync(0xffffffffu, scan, o);
            if (lane >= o) scan += t;
        }
        if (tid == 31) sWs = scan;
        sExc[tid] = scan - v;
    }
    __syncthreads();
    if (tid >= 32 && tid < 64) sExc[tid] += sWs;
    __syncthreads();
    if (valid) {
        int r = atomicAdd(&sCur[b], 1);
        g_perm[sExc[b] + sBase[b] + r] = i;
    }
}

// -------- fused aggregate + bias + relu (+ next-layer GEMV via shuffles) -----
// 8 threads per node, 32 nodes per block, degree-binned permutation.
// Edge indices: lane-distributed LDG (8 consecutive per chunk) + width-8
// shuffle broadcast -> index fan-out moves off the saturated L1tex pipe.
template <bool NEXT>
__global__ void __launch_bounds__(256) k_agg(const float* __restrict__ Hp,
                                             const float* __restrict__ b,
                                             const float* __restrict__ Wn,
                                             float* __restrict__ Out) {
    __shared__ float sW[HD * HD];
    int tid = threadIdx.x;
    if (NEXT) {
        for (int i = tid; i < HD * HD; i += 256) sW[i] = Wn[i];
        __syncthreads();
    }
    int ln = tid >> 3, part = tid & 7;
    int slot = blockIdx.x * 32 + ln;
    if (slot >= NN) return;   // warp-granular (NN%32=16 -> 4-node groups intact)
    int node = g_perm[slot];

    float dd = g_dis[node];
    int s0 = g_nstart[node];
    int deg = DEG(node);
    float4 acc = *(const float4*)(Hp + (size_t)node * HD + part * 4);  // self (pre-scaled)
    float4 acc2 = make_float4(0.f, 0.f, 0.f, 0.f);
    int e = 0;
    // 8-edge chunks: lane 'part' loads one index, broadcast via width-8 shuffle
    for (; e + 8 <= deg; e += 8) {
        int myidx = g_csr[s0 + e + part];
#pragma unroll
        for (int u = 0; u < 8; u += 4) {
            int j0 = __shfl_sync(0xffffffffu, myidx, u + 0, 8);
            int j1 = __shfl_sync(0xffffffffu, myidx, u + 1, 8);
            int j2 = __shfl_sync(0xffffffffu, myidx, u + 2, 8);
            int j3 = __shfl_sync(0xffffffffu, myidx, u + 3, 8);
            const float4 v0 = *(const float4*)(Hp + (size_t)j0 * HD + part * 4);
            const float4 v1 = *(const float4*)(Hp + (size_t)j1 * HD + part * 4);
            const float4 v2 = *(const float4*)(Hp + (size_t)j2 * HD + part * 4);
            const float4 v3 = *(const float4*)(Hp + (size_t)j3 * HD + part * 4);
            acc.x += v0.x + v1.x;  acc2.x += v2.x + v3.x;
            acc.y += v0.y + v1.y;  acc2.y += v2.y + v3.y;
            acc.z += v0.z + v1.z;  acc2.z += v2.z + v3.z;
            acc.w += v0.w + v1.w;  acc2.w += v2.w + v3.w;
        }
    }
    // tail (<8 edges): 4-wide + scalar
    for (; e + 4 <= deg; e += 4) {
        int j0 = g_csr[s0 + e];
        int j1 = g_csr[s0 + e + 1];
        int j2 = g_csr[s0 + e + 2];
        int j3 = g_csr[s0 + e + 3];
        const float4 v0 = *(const float4*)(Hp + (size_t)j0 * HD + part * 4);
        const float4 v1 = *(const float4*)(Hp + (size_t)j1 * HD + part * 4);
        const float4 v2 = *(const float4*)(Hp + (size_t)j2 * HD + part * 4);
        const float4 v3 = *(const float4*)(Hp + (size_t)j3 * HD + part * 4);
        acc.x += v0.x + v1.x;  acc2.x += v2.x + v3.x;
        acc.y += v0.y + v1.y;  acc2.y += v2.y + v3.y;
        acc.z += v0.z + v1.z;  acc2.z += v2.z + v3.z;
        acc.w += v0.w + v1.w;  acc2.w += v2.w + v3.w;
    }
    for (; e < deg; e++) {
        int j0 = g_csr[s0 + e];
        const float4 v0 = *(const float4*)(Hp + (size_t)j0 * HD + part * 4);
        acc.x += v0.x; acc.y += v0.y; acc.z += v0.z; acc.w += v0.w;
    }
    acc.x += acc2.x; acc.y += acc2.y; acc.z += acc2.z; acc.w += acc2.w;
    const float4 bb = *(const float4*)(b + part * 4);
    float h[4];
    h[0] = fmaxf(fmaf(dd, acc.x, bb.x), 0.f);
    h[1] = fmaxf(fmaf(dd, acc.y, bb.y), 0.f);
    h[2] = fmaxf(fmaf(dd, acc.z, bb.z), 0.f);
    h[3] = fmaxf(fmaf(dd, acc.w, bb.w), 0.f);

    if (!NEXT) {
        __stcg((float4*)(Out + (size_t)node * HD + part * 4),
               make_float4(h[0], h[1], h[2], h[3]));
    } else {
        float o[4] = {0.f, 0.f, 0.f, 0.f};
#pragma unroll
        for (int s = 0; s < 8; s++) {
            float q0 = __shfl_sync(0xffffffffu, h[0], s, 8);
            float q1 = __shfl_sync(0xffffffffu, h[1], s, 8);
            float q2 = __shfl_sync(0xffffffffu, h[2], s, 8);
            float q3 = __shfl_sync(0xffffffffu, h[3], s, 8);
            const float4 w0 = *(const float4*)&sW[(4 * s + 0) * HD + part * 4];
            const float4 w1 = *(const float4*)&sW[(4 * s + 1) * HD + part * 4];
            const float4 w2 = *(const float4*)&sW[(4 * s + 2) * HD + part * 4];
            const float4 w3 = *(const float4*)&sW[(4 * s + 3) * HD + part * 4];
            o[0] = fmaf(q0, w0.x, fmaf(q1, w1.x, fmaf(q2, w2.x, fmaf(q3, w3.x, o[0]))));
            o[1] = fmaf(q0, w0.y, fmaf(q1, w1.y, fmaf(q2, w2.y, fmaf(q3, w3.y, o[1]))));
            o[2] = fmaf(q0, w0.z, fmaf(q1, w1.z, fmaf(q2, w2.z, fmaf(q3, w3.z, o[2]))));
            o[3] = fmaf(q0, w0.w, fmaf(q1, w1.w, fmaf(q2, w2.w, fmaf(q3, w3.w, o[3]))));
        }
        __stcg((float4*)(Out + (size_t)node * HD + part * 4),
               make_float4(o[0] * dd, o[1] * dd, o[2] * dd, o[3] * dd));
    }
}

// -------- sort pooling: top-30 per graph by H[:,31] desc, stable by index ----
#define MAXC 1024
__global__ void k_sortpool(const float* __restrict__ H, const int* __restrict__ batch) {
    int g = blockIdx.x;
    int tid = threadIdx.x;  // 128
    __shared__ int sBounds[2];
    __shared__ float keys[MAXC];
    if (tid < 2) {
        int target = g + tid;
        int lo = 0, hi = NN;
        while (lo < hi) {
            int mid = (lo + hi) >> 1;
            if (batch[mid] < target) lo = mid + 1; else hi = mid;
        }
        sBounds[tid] = lo;
    }
    for (int i = tid; i < KK * HD; i += 128)
        g_pool[(size_t)g * KK * HD + i] = 0.f;
    __syncthreads();
    int s = sBounds[0];
    int cnt = sBounds[1] - s;
    bool sh = (cnt <= MAXC);
    if (sh)
        for (int i = tid; i < cnt; i += 128)
            keys[i] = H[(size_t)(s + i) * HD + 31];
    __syncthreads();
    for (int i = tid; i < cnt; i += 128) {
        float ki = sh ? keys[i] : H[(size_t)(s + i) * HD + 31];
        int r = 0;
        for (int j = 0; j < cnt; j++) {
            float kj = sh ? keys[j] : H[(size_t)(s + j) * HD + 31];
            r += (kj > ki) || (kj == ki && j < i);
            if (r >= KK) break;
        }
        if (r < KK) {
            const float4* sp = (const float4*)(H + (size_t)(s + i) * HD);
            float4* dp = (float4*)(g_pool + (size_t)g * KK * HD + r * HD);
#pragma unroll
            for (int q = 0; q < HD / 4; q++) dp[q] = sp[q];
        }
    }
}

// -------- fused conv + fc head: 8 graphs per block, weights loaded once ------
#define GPB 8
__global__ void __launch_bounds__(128) k_convfc(
        const float* __restrict__ cw1, const float* __restrict__ cb1,
        const float* __restrict__ cw2, const float* __restrict__ cb2,
        const float* __restrict__ lw1, const float* __restrict__ lb1,
        const float* __restrict__ lw2, const float* __restrict__ lb2,
        float* __restrict__ out) {
    __shared__ float sPT[HD * 31];
    __shared__ float sw1[16 * 161];
    __shared__ float sw2[32 * 81];
    __shared__ float sC1[16 * 26 + 6];
    __shared__ float sF[GPB * 704];
    __shared__ float sPart[GPB][4];
    int tid = threadIdx.x;  // 128
    int g0 = blockIdx.x * GPB;

    for (int i = tid; i < 16 * 160; i += 128) {
        int o = i / 160, k = i % 160;
        sw1[o * 161 + k] = cw1[i];
    }
    for (int i = tid; i < 32 * 80; i += 128) {
        int o = i / 80, k = i % 80;
        sw2[o * 81 + k] = cw2[i];
    }
    if (tid < HD) sPT[tid * 31 + 30] = 0.f;

    for (int gg = 0; gg < GPB; gg++) {
        int g = g0 + gg;
        __syncthreads();
        for (int i = tid; i < KK * HD; i += 128) {
            int t = i >> 5, c = i & 31;
            sPT[c * 31 + t] = g_pool[(size_t)g * KK * HD + i];
        }
        __syncthreads();

        // conv1
        {
            int o = tid >> 3, g8 = tid & 7;
            int nt = (g8 < 2) ? 4 : 3;
            int t0 = (g8 < 2) ? g8 * 4 : 8 + (g8 - 2) * 3;
            float bias = cb1[o];
            float a0 = bias, a1 = bias, a2 = bias, a3 = bias;
#pragma unroll
            for (int c = 0; c < HD; c++) {
                const float* wp = &sw1[o * 161 + c * 5];
                float w0 = wp[0], w1 = wp[1], w2 = wp[2], w3 = wp[3], w4 = wp[4];
                const float* pp = &sPT[c * 31 + t0];
                float x0 = pp[0], x1 = pp[1], x2 = pp[2], x3 = pp[3];
                float x4 = pp[4], x5 = pp[5], x6 = pp[6], x7 = pp[7];
                a0 = fmaf(w0, x0, fmaf(w1, x1, fmaf(w2, x2, fmaf(w3, x3, fmaf(w4, x4, a0)))));
                a1 = fmaf(w0, x1, fmaf(w1, x2, fmaf(w2, x3, fmaf(w3, x4, fmaf(w4, x5, a1)))));
                a2 = fmaf(w0, x2, fmaf(w1, x3, fmaf(w2, x4, fmaf(w3, x5, fmaf(w4, x6, a2)))));
                a3 = fmaf(w0, x3, fmaf(w1, x4, fmaf(w2, x5, fmaf(w3, x6, fmaf(w4, x7, a3)))));
            }
            sC1[o * 26 + t0 + 0] = fmaxf(a0, 0.f);
            sC1[o * 26 + t0 + 1] = fmaxf(a1, 0.f);
            sC1[o * 26 + t0 + 2] = fmaxf(a2, 0.f);
            if (nt == 4) sC1[o * 26 + t0 + 3] = fmaxf(a3, 0.f);
        }
        __syncthreads();

        // conv2 -> sF
        {
            int o = tid >> 2, g4 = tid & 3;
            int nt = (g4 < 2) ? 6 : 5;
            int t0 = (g4 < 2) ? g4 * 6 : 12 + (g4 - 2) * 5;
            float bias = cb2[o];
            float b0 = bias, b1 = bias, b2 = bias, b3 = bias, b4 = bias, b5 = bias;
#pragma unroll
            for (int c = 0; c < 16; c++) {
                const float* wp = &sw2[o * 81 + c * 5];
                float w0 = wp[0], w1 = wp[1], w2 = wp[2], w3 = wp[3], w4 = wp[4];
                const float* pp = &sC1[c * 26 + t0];
                float x0 = pp[0], x1 = pp[1], x2 = pp[2], x3 = pp[3], x4 = pp[4];
                float x5 = pp[5], x6 = pp[6], x7 = pp[7], x8 = pp[8], x9 = pp[9];
                b0 = fmaf(w0, x0, fmaf(w1, x1, fmaf(w2, x2, fmaf(w3, x3, fmaf(w4, x4, b0)))));
                b1 = fmaf(w0, x1, fmaf(w1, x2, fmaf(w2, x3, fmaf(w3, x4, fmaf(w4, x5, b1)))));
                b2 = fmaf(w0, x2, fmaf(w1, x3, fmaf(w2, x4, fmaf(w3, x5, fmaf(w4, x6, b2)))));
                b3 = fmaf(w0, x3, fmaf(w1, x4, fmaf(w2, x5, fmaf(w3, x6, fmaf(w4, x7, b3)))));
                b4 = fmaf(w0, x4, fmaf(w1, x5, fmaf(w2, x6, fmaf(w3, x7, fmaf(w4, x8, b4)))));
                b5 = fmaf(w0, x5, fmaf(w1, x6, fmaf(w2, x7, fmaf(w3, x8, fmaf(w4, x9, b5)))));
            }
            float* fp = &sF[gg * 704 + o * 22 + t0];
            fp[0] = fmaxf(b0, 0.f);
            fp[1] = fmaxf(b1, 0.f);
            fp[2] = fmaxf(b2, 0.f);
            fp[3] = fmaxf(b3, 0.f);
            fp[4] = fmaxf(b4, 0.f);
            if (nt == 6) fp[5] = fmaxf(b5, 0.f);
        }
    }
    __syncthreads();

    // fc: thread = output j (128), lw1 streamed once for all 8 graphs
    float acc[GPB];
    float bb = lb1[tid];
#pragma unroll
    for (int g = 0; g < GPB; g++) acc[g] = bb;
    for (int i = 0; i < 704; i++) {
        float w = lw1[i * 128 + tid];
#pragma unroll
        for (int g = 0; g < GPB; g++) acc[g] = fmaf(sF[g * 704 + i], w, acc[g]);
    }
    float w2 = lw2[tid];
#pragma unroll
    for (int g = 0; g < GPB; g++) {
        float v = fmaxf(acc[g], 0.f) * w2;
#pragma unroll
        for (int o = 16; o; o >>= 1) v += __shfl_down_sync(0xffffffffu, v, o);
        if ((tid & 31) == 0) sPart[g][tid >> 5] = v;
    }
    __syncthreads();
    if (tid < GPB)
        out[g0 + tid] = sPart[tid][0] + sPart[tid][1] + sPart[tid][2] + sPart[tid][3] + lb2[0];
}

// -------- launch --------
extern "C" void kernel_launch(void* const* d_in, const int* in_sizes, int n_in,
                              void* d_out, int out_size) {
    const float* x = (const float*)d_in[0];
    const int* ei = (const int*)d_in[1];
    const int* batch = (const int*)d_in[2];
    int wi = 3;
    if (n_in > 3 && in_sizes[3] == 1) wi = 4;
    const float* W1  = (const float*)d_in[wi + 0];
    const float* b1  = (const float*)d_in[wi + 1];
    const float* W2  = (const float*)d_in[wi + 2];
    const float* b2  = (const float*)d_in[wi + 3];
    const float* W3  = (const float*)d_in[wi + 4];
    const float* b3  = (const float*)d_in[wi + 5];
    const float* cw1 = (const float*)d_in[wi + 6];
    const float* cb1 = (const float*)d_in[wi + 7];
    const float* cw2 = (const float*)d_in[wi + 8];
    const float* cb2 = (const float*)d_in[wi + 9];
    const float* lw1 = (const float*)d_in[wi + 10];
    const float* lb1 = (const float*)d_in[wi + 11];
    const float* lw2 = (const float*)d_in[wi + 12];
    const float* lb2 = (const float*)d_in[wi + 13];
    float* out = (float*)d_out;
    const int* src = ei;
    const int* dst = ei + EE;

    float *pA, *pB;
    void* pZero;
    cudaGetSymbolAddress((void**)&pA, g_bufA);
    cudaGetSymbolAddress((void**)&pB, g_bufB);
    cudaGetSymbolAddress(&pZero, g_zero);

    cudaMemsetAsync(pZero, 0, (NN + 129) * sizeof(int));
    k_count<<<(EE + 255) / 256, 256>>>(dst);                        // k1
    k_disalloc_mm<<<(NN + 255) / 256, 256>>>(x, W1, pB);            // k2
    k_scatter_permute<<<(EE + 255) / 256, 256>>>(src, dst);         // k3

    const int AGG_GRID = (NN + 31) / 32;
    k_agg<true><<<AGG_GRID, 256>>>(pB, b1, W2, pA);                 // k4 <- profiled
    k_agg<true><<<AGG_GRID, 256>>>(pA, b2, W3, pB);                 // k5
    k_agg<false><<<AGG_GRID, 256>>>(pB, b3, nullptr, pA);           // k6

    k_sortpool<<<GG, 128>>>(pA, batch);                             // k7
    k_convfc<<<GG / GPB, 128>>>(cw1, cb1, cw2, cb2,
                                lw1, lb1, lw2, lb2, out);           // k8
}

// round 17
// speedup vs baseline: 1.1515x; 1.1515x over previous
#include <cuda_runtime.h>

#define NN 250000
#define EE 2500000
#define GG 2048
#define KK 30
#define HD 32

// -------- scratch (static device globals; no runtime allocation) --------
// g_zero: [0,NN)=degcnt, [NN,NN+64)=bins, [NN+64,NN+128)=bincur, [NN+128]=total
__device__ int   g_zero[NN + 129];
#define DEG(i)  g_zero[i]
#define BINS(b) g_zero[NN + (b)]
#define BCUR(b) g_zero[NN + 64 + (b)]
#define TOT     g_zero[NN + 128]
__device__ float g_dis[NN];
__device__ int   g_nstart[NN];
__device__ int   g_cursor[NN];
__device__ int   g_perm[NN];
__device__ int   g_csr[EE];          // src index only (dis folded into features)
__device__ float g_bufA[(size_t)NN * HD];
__device__ float g_bufB[(size_t)NN * HD];
__device__ float g_pool[(size_t)GG * KK * HD];

// -------- prologue --------
__global__ void k_count(const int* __restrict__ dst) {
    int e = blockIdx.x * blockDim.x + threadIdx.x;
    if (e < EE) atomicAdd(&g_zero[dst[e]], 1);   // DEG region
}

// dis + bump allocation (warp-aggregated) + degree histogram + layer-1 dense
__global__ void __launch_bounds__(256) k_disalloc_mm(const float* __restrict__ X,
                                                     const float* __restrict__ W,
                                                     float* __restrict__ Hp) {
    __shared__ float sW[9 * HD];
    __shared__ int sBin[64];
    for (int i = threadIdx.x; i < 9 * HD; i += blockDim.x) sW[i] = W[i];
    if (threadIdx.x < 64) sBin[threadIdx.x] = 0;

    int i = blockIdx.x * blockDim.x + threadIdx.x;
    int lane = threadIdx.x & 31;
    int deg = (i < NN) ? DEG(i) : 0;
    float d = rsqrtf((float)deg + 1.0f);
    if (i < NN) g_dis[i] = d;
    int scan = deg;
#pragma unroll
    for (int o = 1; o < 32; o <<= 1) {
        int t = __shfl_up_sync(0xffffffffu, scan, o);
        if (lane >= o) scan += t;
    }
    int wsum = __shfl_sync(0xffffffffu, scan, 31);
    int base = 0;
    if (lane == 31) base = atomicAdd(&TOT, wsum);
    base = __shfl_sync(0xffffffffu, base, 31);
    int st = base + scan - deg;
    if (i < NN) {
        g_nstart[i] = st;
        g_cursor[i] = st;
    }
    __syncthreads();
    if (i < NN) atomicAdd(&sBin[deg < 63 ? deg : 63], 1);
    __syncthreads();
    if (threadIdx.x < 64 && sBin[threadIdx.x]) atomicAdd(&BINS(threadIdx.x), sBin[threadIdx.x]);
    if (i >= NN) return;

    float xin[9];
#pragma unroll
    for (int k = 0; k < 9; k++) xin[k] = X[(size_t)i * 9 + k];
    float out[HD];
#pragma unroll
    for (int f = 0; f < HD; f++) {
        float acc = 0.f;
#pragma unroll
        for (int k = 0; k < 9; k++) acc = fmaf(xin[k], sW[k * HD + f], acc);
        out[f] = acc * d;
    }
    float4* ph = (float4*)(Hp + (size_t)i * HD);
#pragma unroll
    for (int q = 0; q < HD / 4; q++) ph[q] = ((float4*)out)[q];
}

// CSR scatter (edge-parallel) + degree-bin permutation (node-parallel) fused.
__global__ void __launch_bounds__(256) k_scatter_permute(const int* __restrict__ src,
                                                         const int* __restrict__ dst) {
    __shared__ int sCnt[64];
    __shared__ int sCur[64];
    __shared__ int sBase[64];
    __shared__ int sExc[64];
    __shared__ int sWs;
    int tid = threadIdx.x;
    if (tid < 64) { sCnt[tid] = 0; sCur[tid] = 0; }

    // edge part
    int e = blockIdx.x * blockDim.x + tid;
    if (e < EE) {
        int d = dst[e];
        int p = atomicAdd(&g_cursor[d], 1);
        g_csr[p] = src[e];
    }

    // node part
    int i = e;
    bool valid = i < NN;
    __syncthreads();
    int b = 0;
    if (valid) {
        int deg = DEG(i);
        b = deg < 63 ? deg : 63;
        atomicAdd(&sCnt[b], 1);
    }
    __syncthreads();
    if (tid < 64) {
        int c = sCnt[tid];
        sBase[tid] = c ? atomicAdd(&BCUR(tid), c) : 0;
        int v = BINS(tid);
        int lane = tid & 31;
        int scan = v;
#pragma unroll
        for (int o = 1; o < 32; o <<= 1) {
            int t = __shfl_up_sync(0xffffffffu, scan, o);
            if (lane >= o) scan += t;
        }
        if (tid == 31) sWs = scan;
        sExc[tid] = scan - v;
    }
    __syncthreads();
    if (tid >= 32 && tid < 64) sExc[tid] += sWs;
    __syncthreads();
    if (valid) {
        int r = atomicAdd(&sCur[b], 1);
        g_perm[sExc[b] + sBase[b] + r] = i;
    }
}

// -------- fused aggregate + bias + relu (+ next-layer GEMV via shuffles) -----
// 8 threads per node, 32 nodes per block, degree-binned permutation.
// R15 form: scalar 4-wide index loads, 32 regs, ~89% occ — measured best.
template <bool NEXT>
__global__ void __launch_bounds__(256) k_agg(const float* __restrict__ Hp,
                                             const float* __restrict__ b,
                                             const float* __restrict__ Wn,
                                             float* __restrict__ Out) {
    __shared__ float sW[HD * HD];
    int tid = threadIdx.x;
    if (NEXT) {
        for (int i = tid; i < HD * HD; i += 256) sW[i] = Wn[i];
        __syncthreads();
    }
    int ln = tid >> 3, part = tid & 7;
    int slot = blockIdx.x * 32 + ln;
    if (slot >= NN) return;   // warp-granular (NN%32=16 -> 4-node groups intact)
    int node = g_perm[slot];

    float dd = g_dis[node];
    int s0 = g_nstart[node];
    int deg = DEG(node);
    float4 acc = *(const float4*)(Hp + (size_t)node * HD + part * 4);  // self (pre-scaled)
    float4 acc2 = make_float4(0.f, 0.f, 0.f, 0.f);
    int e = 0;
    for (; e + 4 <= deg; e += 4) {
        int j0 = g_csr[s0 + e];
        int j1 = g_csr[s0 + e + 1];
        int j2 = g_csr[s0 + e + 2];
        int j3 = g_csr[s0 + e + 3];
        const float4 v0 = *(const float4*)(Hp + (size_t)j0 * HD + part * 4);
        const float4 v1 = *(const float4*)(Hp + (size_t)j1 * HD + part * 4);
        const float4 v2 = *(const float4*)(Hp + (size_t)j2 * HD + part * 4);
        const float4 v3 = *(const float4*)(Hp + (size_t)j3 * HD + part * 4);
        acc.x += v0.x + v1.x;  acc2.x += v2.x + v3.x;
        acc.y += v0.y + v1.y;  acc2.y += v2.y + v3.y;
        acc.z += v0.z + v1.z;  acc2.z += v2.z + v3.z;
        acc.w += v0.w + v1.w;  acc2.w += v2.w + v3.w;
    }
    for (; e < deg; e++) {
        int j0 = g_csr[s0 + e];
        const float4 v0 = *(const float4*)(Hp + (size_t)j0 * HD + part * 4);
        acc.x += v0.x; acc.y += v0.y; acc.z += v0.z; acc.w += v0.w;
    }
    acc.x += acc2.x; acc.y += acc2.y; acc.z += acc2.z; acc.w += acc2.w;
    const float4 bb = *(const float4*)(b + part * 4);
    float h[4];
    h[0] = fmaxf(fmaf(dd, acc.x, bb.x), 0.f);
    h[1] = fmaxf(fmaf(dd, acc.y, bb.y), 0.f);
    h[2] = fmaxf(fmaf(dd, acc.z, bb.z), 0.f);
    h[3] = fmaxf(fmaf(dd, acc.w, bb.w), 0.f);

    if (!NEXT) {
        __stcg((float4*)(Out + (size_t)node * HD + part * 4),
               make_float4(h[0], h[1], h[2], h[3]));
    } else {
        float o[4] = {0.f, 0.f, 0.f, 0.f};
#pragma unroll
        for (int s = 0; s < 8; s++) {
            float q0 = __shfl_sync(0xffffffffu, h[0], s, 8);
            float q1 = __shfl_sync(0xffffffffu, h[1], s, 8);
            float q2 = __shfl_sync(0xffffffffu, h[2], s, 8);
            float q3 = __shfl_sync(0xffffffffu, h[3], s, 8);
            const float4 w0 = *(const float4*)&sW[(4 * s + 0) * HD + part * 4];
            const float4 w1 = *(const float4*)&sW[(4 * s + 1) * HD + part * 4];
            const float4 w2 = *(const float4*)&sW[(4 * s + 2) * HD + part * 4];
            const float4 w3 = *(const float4*)&sW[(4 * s + 3) * HD + part * 4];
            o[0] = fmaf(q0, w0.x, fmaf(q1, w1.x, fmaf(q2, w2.x, fmaf(q3, w3.x, o[0]))));
            o[1] = fmaf(q0, w0.y, fmaf(q1, w1.y, fmaf(q2, w2.y, fmaf(q3, w3.y, o[1]))));
            o[2] = fmaf(q0, w0.z, fmaf(q1, w1.z, fmaf(q2, w2.z, fmaf(q3, w3.z, o[2]))));
            o[3] = fmaf(q0, w0.w, fmaf(q1, w1.w, fmaf(q2, w2.w, fmaf(q3, w3.w, o[3]))));
        }
        __stcg((float4*)(Out + (size_t)node * HD + part * 4),
               make_float4(o[0] * dd, o[1] * dd, o[2] * dd, o[3] * dd));
    }
}

// -------- sort pooling: top-30 per graph by H[:,31] desc, stable by index ----
// zero-fill only when cnt < KK (rows below min(cnt,KK) are always overwritten)
#define MAXC 1024
__global__ void k_sortpool(const float* __restrict__ H, const int* __restrict__ batch) {
    int g = blockIdx.x;
    int tid = threadIdx.x;  // 128
    __shared__ int sBounds[2];
    __shared__ float keys[MAXC];
    if (tid < 2) {
        int target = g + tid;
        int lo = 0, hi = NN;
        while (lo < hi) {
            int mid = (lo + hi) >> 1;
            if (batch[mid] < target) lo = mid + 1; else hi = mid;
        }
        sBounds[tid] = lo;
    }
    __syncthreads();
    int s = sBounds[0];
    int cnt = sBounds[1] - s;
    if (cnt < KK) {   // rare: only then do zero rows remain
        for (int i = tid; i < KK * HD; i += 128)
            g_pool[(size_t)g * KK * HD + i] = 0.f;
    }
    bool sh = (cnt <= MAXC);
    if (sh)
        for (int i = tid; i < cnt; i += 128)
            keys[i] = H[(size_t)(s + i) * HD + 31];
    __syncthreads();
    for (int i = tid; i < cnt; i += 128) {
        float ki = sh ? keys[i] : H[(size_t)(s + i) * HD + 31];
        int r = 0;
        for (int j = 0; j < cnt; j++) {
            float kj = sh ? keys[j] : H[(size_t)(s + j) * HD + 31];
            r += (kj > ki) || (kj == ki && j < i);
            if (r >= KK) break;
        }
        if (r < KK) {
            const float4* sp = (const float4*)(H + (size_t)(s + i) * HD);
            float4* dp = (float4*)(g_pool + (size_t)g * KK * HD + r * HD);
#pragma unroll
            for (int q = 0; q < HD / 4; q++) dp[q] = sp[q];
        }
    }
}

// -------- fused conv + fc head: 4 graphs per block (512 blocks) --------
#define GPB 4
__global__ void __launch_bounds__(128) k_convfc(
        const float* __restrict__ cw1, const float* __restrict__ cb1,
        const float* __restrict__ cw2, const float* __restrict__ cb2,
        const float* __restrict__ lw1, const float* __restrict__ lb1,
        const float* __restrict__ lw2, const float* __restrict__ lb2,
        float* __restrict__ out) {
    __shared__ float sPT[HD * 31];       // 3968B
    __shared__ float sw1[16 * 161];      // 10304B
    __shared__ float sw2[32 * 81];       // 10368B
    __shared__ float sC1[16 * 26 + 6];   // 1688B
    __shared__ float sF[GPB * 704];      // 11264B
    __shared__ float sPart[GPB][4];      // 64B   -> ~37.7KB total
    int tid = threadIdx.x;  // 128
    int g0 = blockIdx.x * GPB;

    for (int i = tid; i < 16 * 160; i += 128) {
        int o = i / 160, k = i % 160;
        sw1[o * 161 + k] = cw1[i];
    }
    for (int i = tid; i < 32 * 80; i += 128) {
        int o = i / 80, k = i % 80;
        sw2[o * 81 + k] = cw2[i];
    }
    if (tid < HD) sPT[tid * 31 + 30] = 0.f;

    for (int gg = 0; gg < GPB; gg++) {
        int g = g0 + gg;
        __syncthreads();
        for (int i = tid; i < KK * HD; i += 128) {
            int t = i >> 5, c = i & 31;
            sPT[c * 31 + t] = g_pool[(size_t)g * KK * HD + i];
        }
        __syncthreads();

        // conv1
        {
            int o = tid >> 3, g8 = tid & 7;
            int nt = (g8 < 2) ? 4 : 3;
            int t0 = (g8 < 2) ? g8 * 4 : 8 + (g8 - 2) * 3;
            float bias = cb1[o];
            float a0 = bias, a1 = bias, a2 = bias, a3 = bias;
#pragma unroll
            for (int c = 0; c < HD; c++) {
                const float* wp = &sw1[o * 161 + c * 5];
                float w0 = wp[0], w1 = wp[1], w2 = wp[2], w3 = wp[3], w4 = wp[4];
                const float* pp = &sPT[c * 31 + t0];
                float x0 = pp[0], x1 = pp[1], x2 = pp[2], x3 = pp[3];
                float x4 = pp[4], x5 = pp[5], x6 = pp[6], x7 = pp[7];
                a0 = fmaf(w0, x0, fmaf(w1, x1, fmaf(w2, x2, fmaf(w3, x3, fmaf(w4, x4, a0)))));
                a1 = fmaf(w0, x1, fmaf(w1, x2, fmaf(w2, x3, fmaf(w3, x4, fmaf(w4, x5, a1)))));
                a2 = fmaf(w0, x2, fmaf(w1, x3, fmaf(w2, x4, fmaf(w3, x5, fmaf(w4, x6, a2)))));
                a3 = fmaf(w0, x3, fmaf(w1, x4, fmaf(w2, x5, fmaf(w3, x6, fmaf(w4, x7, a3)))));
            }
            sC1[o * 26 + t0 + 0] = fmaxf(a0, 0.f);
            sC1[o * 26 + t0 + 1] = fmaxf(a1, 0.f);
            sC1[o * 26 + t0 + 2] = fmaxf(a2, 0.f);
            if (nt == 4) sC1[o * 26 + t0 + 3] = fmaxf(a3, 0.f);
        }
        __syncthreads();

        // conv2 -> sF
        {
            int o = tid >> 2, g4 = tid & 3;
            int nt = (g4 < 2) ? 6 : 5;
            int t0 = (g4 < 2) ? g4 * 6 : 12 + (g4 - 2) * 5;
            float bias = cb2[o];
            float b0 = bias, b1 = bias, b2 = bias, b3 = bias, b4 = bias, b5 = bias;
#pragma unroll
            for (int c = 0; c < 16; c++) {
                const float* wp = &sw2[o * 81 + c * 5];
                float w0 = wp[0], w1 = wp[1], w2 = wp[2], w3 = wp[3], w4 = wp[4];
                const float* pp = &sC1[c * 26 + t0];
                float x0 = pp[0], x1 = pp[1], x2 = pp[2], x3 = pp[3], x4 = pp[4];
                float x5 = pp[5], x6 = pp[6], x7 = pp[7], x8 = pp[8], x9 = pp[9];
                b0 = fmaf(w0, x0, fmaf(w1, x1, fmaf(w2, x2, fmaf(w3, x3, fmaf(w4, x4, b0)))));
                b1 = fmaf(w0, x1, fmaf(w1, x2, fmaf(w2, x3, fmaf(w3, x4, fmaf(w4, x5, b1)))));
                b2 = fmaf(w0, x2, fmaf(w1, x3, fmaf(w2, x4, fmaf(w3, x5, fmaf(w4, x6, b2)))));
                b3 = fmaf(w0, x3, fmaf(w1, x4, fmaf(w2, x5, fmaf(w3, x6, fmaf(w4, x7, b3)))));
                b4 = fmaf(w0, x4, fmaf(w1, x5, fmaf(w2, x6, fmaf(w3, x7, fmaf(w4, x8, b4)))));
                b5 = fmaf(w0, x5, fmaf(w1, x6, fmaf(w2, x7, fmaf(w3, x8, fmaf(w4, x9, b5)))));
            }
            float* fp = &sF[gg * 704 + o * 22 + t0];
            fp[0] = fmaxf(b0, 0.f);
            fp[1] = fmaxf(b1, 0.f);
            fp[2] = fmaxf(b2, 0.f);
            fp[3] = fmaxf(b3, 0.f);
            fp[4] = fmaxf(b4, 0.f);
            if (nt == 6) fp[5] = fmaxf(b5, 0.f);
        }
    }
    __syncthreads();

    // fc: thread = output j (128), lw1 streamed once for all GPB graphs
    float acc[GPB];
    float bb = lb1[tid];
#pragma unroll
    for (int g = 0; g < GPB; g++) acc[g] = bb;
    for (int i = 0; i < 704; i++) {
        float w = lw1[i * 128 + tid];
#pragma unroll
        for (int g = 0; g < GPB; g++) acc[g] = fmaf(sF[g * 704 + i], w, acc[g]);
    }
    float w2 = lw2[tid];
#pragma unroll
    for (int g = 0; g < GPB; g++) {
        float v = fmaxf(acc[g], 0.f) * w2;
#pragma unroll
        for (int o = 16; o; o >>= 1) v += __shfl_down_sync(0xffffffffu, v, o);
        if ((tid & 31) == 0) sPart[g][tid >> 5] = v;
    }
    __syncthreads();
    if (tid < GPB)
        out[g0 + tid] = sPart[tid][0] + sPart[tid][1] + sPart[tid][2] + sPart[tid][3] + lb2[0];
}

// -------- launch --------
extern "C" void kernel_launch(void* const* d_in, const int* in_sizes, int n_in,
                              void* d_out, int out_size) {
    const float* x = (const float*)d_in[0];
    const int* ei = (const int*)d_in[1];
    const int* batch = (const int*)d_in[2];
    int wi = 3;
    if (n_in > 3 && in_sizes[3] == 1) wi = 4;
    const float* W1  = (const float*)d_in[wi + 0];
    const float* b1  = (const float*)d_in[wi + 1];
    const float* W2  = (const float*)d_in[wi + 2];
    const float* b2  = (const float*)d_in[wi + 3];
    const float* W3  = (const float*)d_in[wi + 4];
    const float* b3  = (const float*)d_in[wi + 5];
    const float* cw1 = (const float*)d_in[wi + 6];
    const float* cb1 = (const float*)d_in[wi + 7];
    const float* cw2 = (const float*)d_in[wi + 8];
    const float* cb2 = (const float*)d_in[wi + 9];
    const float* lw1 = (const float*)d_in[wi + 10];
    const float* lb1 = (const float*)d_in[wi + 11];
    const float* lw2 = (const float*)d_in[wi + 12];
    const float* lb2 = (const float*)d_in[wi + 13];
    float* out = (float*)d_out;
    const int* src = ei;
    const int* dst = ei + EE;

    float *pA, *pB;
    void* pZero;
    cudaGetSymbolAddress((void**)&pA, g_bufA);
    cudaGetSymbolAddress((void**)&pB, g_bufB);
    cudaGetSymbolAddress(&pZero, g_zero);

    cudaMemsetAsync(pZero, 0, (NN + 129) * sizeof(int));
    k_count<<<(EE + 255) / 256, 256>>>(dst);                        // k1
    k_disalloc_mm<<<(NN + 255) / 256, 256>>>(x, W1, pB);            // k2
    k_scatter_permute<<<(EE + 255) / 256, 256>>>(src, dst);         // k3

    const int AGG_GRID = (NN + 31) / 32;
    k_agg<true><<<AGG_GRID, 256>>>(pB, b1, W2, pA);                 // k4 <- profiled
    k_agg<true><<<AGG_GRID, 256>>>(pA, b2, W3, pB);                 // k5
    k_agg<false><<<AGG_GRID, 256>>>(pB, b3, nullptr, pA);           // k6

    k_sortpool<<<GG, 128>>>(pA, batch);                             // k7
    k_convfc<<<GG / GPB, 128>>>(cw1, cb1, cw2, cb2,
                                lw1, lb1, lw2, lb2, out);           // k8
}